// round 16
// baseline (speedup 1.0000x reference)
#include <cuda_runtime.h>
#include <cuda_bf16.h>
#include <cstdint>

// AtomicComposition: counts[s][k] = #atoms in structure s with species == all_species[k]
// species:            d_in[2]  int32  [n_atoms]
// structure_offsets:  d_in[8]  int32 OR int64 [n_structures] (CSR starts) -- dtype probed on device
// all_species:        d_in[9]  int32  [n_species]
// out: float32 [n_structures, n_species]

__device__ __forceinline__ bool probe_is64(const void* offs, int n_structures,
                                           long long n_atoms) {
    if (n_structures <= 1) return true;
    const long long probe = ((const long long*)offs)[1];
    return (probe >= 0 && probe <= n_atoms);
}

__device__ __forceinline__ int load_offset32(const void* offs, int i, bool is64) {
    if (is64) return (int)((const long long*)offs)[i];
    return ((const int*)offs)[i];
}

// pack low bytes of 4 ints into one word: [x.b0, y.b0, z.b0, w.b0]
__device__ __forceinline__ unsigned pack_bytes(const int4 v) {
    const unsigned t0 = __byte_perm((unsigned)v.x, (unsigned)v.y, 0x0040);
    const unsigned t1 = __byte_perm((unsigned)v.z, (unsigned)v.w, 0x0040);
    return __byte_perm(t0, t1, 0x5410);
}

// NS=5. One warp owns 2 consecutive structures. 4 front-batched LDG.128 via
// __ldcg (L2-cached, L1-bypass: zero reuse stream, keeps L2 warm for replays),
// dp4a byte-SIMD counting, packed dual-REDUX, lanes 0-4 store.
__global__ __launch_bounds__(256) void atomic_composition_g2(
    const int* __restrict__ species,
    const void* __restrict__ offsets,
    const int* __restrict__ all_species,
    float* __restrict__ out,
    int n_structures,
    int n_atoms)
{
    const int tid   = threadIdx.x;
    const int gwarp = (blockIdx.x * blockDim.x + tid) >> 5;
    const int lid   = tid & 31;
    const int s0    = gwarp * 2;
    if (s0 >= n_structures) return;

    const bool is64 = probe_is64(offsets, n_structures, (long long)n_atoms);

    // offsets[s0 .. s0+2] loaded lane-parallel, distributed by shfl
    int my_off = n_atoms;
    if (lid <= 2) {
        const int idx = s0 + lid;
        my_off = (idx < n_structures) ? load_offset32(offsets, idx, is64) : n_atoms;
    }
    const int start0 = __shfl_sync(0xFFFFFFFFu, my_off, 0);

    const int sp0 = __ldg(&all_species[0]);
    const int sp1 = __ldg(&all_species[1]);
    const int sp2 = __ldg(&all_species[2]);
    const int sp3 = __ldg(&all_species[3]);
    const int sp4 = __ldg(&all_species[4]);

    // uniform fast path: 2 contiguous structures of exactly 256 atoms each
    const bool uni = __all_sync(0xFFFFFFFFu,
                                (lid > 2) || (my_off == start0 + lid * 256));

    if (uni && (s0 + 2 <= n_structures) && ((start0 & 3) == 0)) {
        const int4* __restrict__ B = reinterpret_cast<const int4*>(species + start0);

        // 4 independent LDG.128, L1-bypass / L2-cacheable
        int4 A[4];
#pragma unroll
        for (int i = 0; i < 4; ++i) A[i] = __ldcg(&B[i * 32 + lid]);

        // byte-SIMD valid only if all values fit in a byte (true here: z<119)
        int orall = 0;
#pragma unroll
        for (int i = 0; i < 4; ++i)
            orall |= A[i].x | A[i].y | A[i].z | A[i].w;
        const bool bytesafe = __all_sync(0xFFFFFFFFu, (orall & ~0xFF) == 0 && orall >= 0);

        if (bytesafe) {
            const unsigned q0 = (unsigned)sp0 * 0x01010101u;
            const unsigned q1 = (unsigned)sp1 * 0x01010101u;
            const unsigned q2 = (unsigned)sp2 * 0x01010101u;
            const unsigned q3 = (unsigned)sp3 * 0x01010101u;
            const unsigned q4 = (unsigned)sp4 * 0x01010101u;
            const int ONE = 0x01010101;

#pragma unroll
            for (int g = 0; g < 2; ++g) {
                const unsigned w0 = pack_bytes(A[2 * g]);
                const unsigned w1 = pack_bytes(A[2 * g + 1]);

                int c0 = 0, c1 = 0, c2 = 0, c3 = 0, c4 = 0;
                c0 = __dp4a((int)__vcmpeq4(w0, q0), ONE, c0);
                c1 = __dp4a((int)__vcmpeq4(w0, q1), ONE, c1);
                c2 = __dp4a((int)__vcmpeq4(w0, q2), ONE, c2);
                c3 = __dp4a((int)__vcmpeq4(w0, q3), ONE, c3);
                c4 = __dp4a((int)__vcmpeq4(w0, q4), ONE, c4);
                c0 = __dp4a((int)__vcmpeq4(w1, q0), ONE, c0);
                c1 = __dp4a((int)__vcmpeq4(w1, q1), ONE, c1);
                c2 = __dp4a((int)__vcmpeq4(w1, q2), ONE, c2);
                c3 = __dp4a((int)__vcmpeq4(w1, q3), ONE, c3);
                c4 = __dp4a((int)__vcmpeq4(w1, q4), ONE, c4);

                // counts = -c; per-lane <= 8, warp sums <= 256 -> 10-bit fields
                int pA = (-c0) | ((-c1) << 10) | ((-c2) << 20);
                int pB = (-c3) | ((-c4) << 10);
                pA = __reduce_add_sync(0xFFFFFFFFu, pA);
                pB = __reduce_add_sync(0xFFFFFFFFu, pB);

                const int word = (lid < 3) ? pA : pB;
                const int sh   = (lid < 3) ? (10 * lid) : (10 * (lid - 3));
                if (lid < 5)
                    out[(s0 + g) * 5 + lid] = (float)((word >> sh) & 1023);
            }
            return;
        }

        // rare: values exceed a byte -> scalar compares on registers
#pragma unroll
        for (int g = 0; g < 2; ++g) {
            const int4 u = A[2 * g];
            const int4 v = A[2 * g + 1];
            int c0 = (u.x==sp0)+(u.y==sp0)+(u.z==sp0)+(u.w==sp0)
                   + (v.x==sp0)+(v.y==sp0)+(v.z==sp0)+(v.w==sp0);
            int c1 = (u.x==sp1)+(u.y==sp1)+(u.z==sp1)+(u.w==sp1)
                   + (v.x==sp1)+(v.y==sp1)+(v.z==sp1)+(v.w==sp1);
            int c2 = (u.x==sp2)+(u.y==sp2)+(u.z==sp2)+(u.w==sp2)
                   + (v.x==sp2)+(v.y==sp2)+(v.z==sp2)+(v.w==sp2);
            int c3 = (u.x==sp3)+(u.y==sp3)+(u.z==sp3)+(u.w==sp3)
                   + (v.x==sp3)+(v.y==sp3)+(v.z==sp3)+(v.w==sp3);
            int c4 = (u.x==sp4)+(u.y==sp4)+(u.z==sp4)+(u.w==sp4)
                   + (v.x==sp4)+(v.y==sp4)+(v.z==sp4)+(v.w==sp4);
            int pA = c0 | (c1 << 10) | (c2 << 20);
            int pB = c3 | (c4 << 10);
            pA = __reduce_add_sync(0xFFFFFFFFu, pA);
            pB = __reduce_add_sync(0xFFFFFFFFu, pB);
            const int word = (lid < 3) ? pA : pB;
            const int sh   = (lid < 3) ? (10 * lid) : (10 * (lid - 3));
            if (lid < 5)
                out[(s0 + g) * 5 + lid] = (float)((word >> sh) & 1023);
        }
        return;
    }

    // general fallback: per-structure loop (any sizes/alignment)
    for (int g = 0; g < 2; ++g) {
        const int s = s0 + g;
        if (s >= n_structures) break;
        const int start = __shfl_sync(0xFFFFFFFFu, my_off, g);
        const int end   = __shfl_sync(0xFFFFFFFFu, my_off, g + 1);

        int c0 = 0, c1 = 0, c2 = 0, c3 = 0, c4 = 0;
        for (int j = start + lid; j < end; j += 32) {
            const int z = species[j];
            c0 += (z == sp0); c1 += (z == sp1); c2 += (z == sp2);
            c3 += (z == sp3); c4 += (z == sp4);
        }
        c0 = __reduce_add_sync(0xFFFFFFFFu, c0);
        c1 = __reduce_add_sync(0xFFFFFFFFu, c1);
        c2 = __reduce_add_sync(0xFFFFFFFFu, c2);
        c3 = __reduce_add_sync(0xFFFFFFFFu, c3);
        c4 = __reduce_add_sync(0xFFFFFFFFu, c4);
        if (lid == 0) {
            float* o = out + s * 5;
            o[0] = (float)c0; o[1] = (float)c1; o[2] = (float)c2;
            o[3] = (float)c3; o[4] = (float)c4;
        }
    }
}

// Fallback for arbitrary n_species (shared-memory counters, CTA per structure)
__global__ __launch_bounds__(64) void atomic_composition_generic(
    const int* __restrict__ species,
    const void* __restrict__ offsets,
    const int* __restrict__ all_species,
    float* __restrict__ out,
    int n_structures,
    long long n_atoms,
    int n_species)
{
    extern __shared__ int shc[];
    const int s   = blockIdx.x;
    const int tid = threadIdx.x;
    for (int k = tid; k < n_species; k += 64) shc[k] = 0;
    __syncthreads();

    const bool is64 = probe_is64(offsets, n_structures, n_atoms);
    const long long start = is64 ? ((const long long*)offsets)[s]
                                 : (long long)((const int*)offsets)[s];
    long long end = n_atoms;
    if (s + 1 < n_structures)
        end = is64 ? ((const long long*)offsets)[s + 1]
                   : (long long)((const int*)offsets)[s + 1];

    for (long long j = start + tid; j < end; j += 64) {
        const int z = species[j];
        for (int k = 0; k < n_species; ++k)
            if (z == __ldg(&all_species[k])) atomicAdd(&shc[k], 1);
    }
    __syncthreads();
    for (int k = tid; k < n_species; k += 64)
        out[(long long)s * n_species + k] = (float)shc[k];
}

extern "C" void kernel_launch(void* const* d_in, const int* in_sizes, int n_in,
                              void* d_out, int out_size)
{
    const int*  species     = (const int*)d_in[2];
    const void* offsets     = d_in[8];
    const int*  all_species = (const int*)d_in[9];
    float*      out         = (float*)d_out;

    const long long n_atoms      = (long long)in_sizes[2];
    const int       n_structures = in_sizes[8];
    const int       n_species    = in_sizes[9];

    if (n_species == 5 && n_atoms < 0x7FFFFFFFLL) {
        const int warps = (n_structures + 1) / 2;        // 16384
        const int ctas  = (warps * 32 + 255) / 256;      // 2048 CTAs
        atomic_composition_g2<<<ctas, 256>>>(
            species, offsets, all_species, out, n_structures, (int)n_atoms);
    } else {
        atomic_composition_generic<<<n_structures, 64, n_species * sizeof(int)>>>(
            species, offsets, all_species, out, n_structures, n_atoms, n_species);
    }
}

// round 17
// speedup vs baseline: 1.0239x; 1.0239x over previous
#include <cuda_runtime.h>
#include <cuda_bf16.h>
#include <cstdint>

// AtomicComposition: counts[s][k] = #atoms in structure s with species == all_species[k]
// species:            d_in[2]  int32  [n_atoms]
// structure_offsets:  d_in[8]  int32 OR int64 [n_structures] (CSR starts) -- dtype probed on device
// all_species:        d_in[9]  int32  [n_species]
// out: float32 [n_structures, n_species]
//
// Converged design: warp-per-4-structures, 8 front-batched LDG.128 (__ldcg),
// byte-SIMD counting (vcmpeq4+dp4a), packed dual-REDUX, lanes 0-4 store.
// Eleven structural variants (MLP 2..16, LDS-LUT, cp.async, bulk TMA,
// pipelines, occupancy 21..79%) all land at 10.75-11.0us: the residual is an
// environment floor (launch/DVFS), not kernel-schedulable time.

__device__ __forceinline__ bool probe_is64(const void* offs, int n_structures,
                                           long long n_atoms) {
    if (n_structures <= 1) return true;
    const long long probe = ((const long long*)offs)[1];
    return (probe >= 0 && probe <= n_atoms);
}

__device__ __forceinline__ int load_offset32(const void* offs, int i, bool is64) {
    if (is64) return (int)((const long long*)offs)[i];
    return ((const int*)offs)[i];
}

// pack low bytes of 4 ints into one word: [x.b0, y.b0, z.b0, w.b0]
__device__ __forceinline__ unsigned pack_bytes(const int4 v) {
    const unsigned t0 = __byte_perm((unsigned)v.x, (unsigned)v.y, 0x0040);
    const unsigned t1 = __byte_perm((unsigned)v.z, (unsigned)v.w, 0x0040);
    return __byte_perm(t0, t1, 0x5410);
}

__global__ __launch_bounds__(512) void atomic_composition_simd(
    const int* __restrict__ species,
    const void* __restrict__ offsets,
    const int* __restrict__ all_species,
    float* __restrict__ out,
    int n_structures,
    int n_atoms)
{
    const int tid   = threadIdx.x;
    const int gwarp = (blockIdx.x * blockDim.x + tid) >> 5;
    const int lid   = tid & 31;
    const int s0    = gwarp * 4;
    if (s0 >= n_structures) return;

    const bool is64 = probe_is64(offsets, n_structures, (long long)n_atoms);

    // offsets[s0 .. s0+4] loaded lane-parallel, distributed by shfl
    int my_off = n_atoms;
    if (lid <= 4) {
        const int idx = s0 + lid;
        my_off = (idx < n_structures) ? load_offset32(offsets, idx, is64) : n_atoms;
    }
    const int start0 = __shfl_sync(0xFFFFFFFFu, my_off, 0);

    const int sp0 = __ldg(&all_species[0]);
    const int sp1 = __ldg(&all_species[1]);
    const int sp2 = __ldg(&all_species[2]);
    const int sp3 = __ldg(&all_species[3]);
    const int sp4 = __ldg(&all_species[4]);

    // uniform fast path: 4 contiguous structures of exactly 256 atoms each
    const bool uni = __all_sync(0xFFFFFFFFu,
                                (lid > 4) || (my_off == start0 + lid * 256));

    if (uni && (s0 + 4 <= n_structures) && ((start0 & 3) == 0)) {
        const int4* __restrict__ B = reinterpret_cast<const int4*>(species + start0);

        // 8 independent LDG.128 (L1-bypass / L2-cacheable), front-batched
        int4 A[8];
#pragma unroll
        for (int i = 0; i < 8; ++i) A[i] = __ldcg(&B[i * 32 + lid]);

        // byte-SIMD valid only if every value fits in a byte (true here: z<119)
        int orall = 0;
#pragma unroll
        for (int i = 0; i < 8; ++i)
            orall |= A[i].x | A[i].y | A[i].z | A[i].w;
        const bool bytesafe = __all_sync(0xFFFFFFFFu, (orall & ~0xFF) == 0 && orall >= 0);

        if (bytesafe) {
            const unsigned q0 = (unsigned)sp0 * 0x01010101u;
            const unsigned q1 = (unsigned)sp1 * 0x01010101u;
            const unsigned q2 = (unsigned)sp2 * 0x01010101u;
            const unsigned q3 = (unsigned)sp3 * 0x01010101u;
            const unsigned q4 = (unsigned)sp4 * 0x01010101u;
            const int ONE = 0x01010101;

#pragma unroll
            for (int g = 0; g < 4; ++g) {
                const unsigned w0 = pack_bytes(A[2 * g]);
                const unsigned w1 = pack_bytes(A[2 * g + 1]);

                // dp4a over 0xFF(-1) match bytes: c accumulates -(count)
                int c0 = 0, c1 = 0, c2 = 0, c3 = 0, c4 = 0;
                c0 = __dp4a((int)__vcmpeq4(w0, q0), ONE, c0);
                c1 = __dp4a((int)__vcmpeq4(w0, q1), ONE, c1);
                c2 = __dp4a((int)__vcmpeq4(w0, q2), ONE, c2);
                c3 = __dp4a((int)__vcmpeq4(w0, q3), ONE, c3);
                c4 = __dp4a((int)__vcmpeq4(w0, q4), ONE, c4);
                c0 = __dp4a((int)__vcmpeq4(w1, q0), ONE, c0);
                c1 = __dp4a((int)__vcmpeq4(w1, q1), ONE, c1);
                c2 = __dp4a((int)__vcmpeq4(w1, q2), ONE, c2);
                c3 = __dp4a((int)__vcmpeq4(w1, q3), ONE, c3);
                c4 = __dp4a((int)__vcmpeq4(w1, q4), ONE, c4);

                // counts = -c; per-lane <= 8, warp sums <= 256 -> 10-bit fields
                int pA = (-c0) | ((-c1) << 10) | ((-c2) << 20);
                int pB = (-c3) | ((-c4) << 10);
                pA = __reduce_add_sync(0xFFFFFFFFu, pA);
                pB = __reduce_add_sync(0xFFFFFFFFu, pB);

                const int word = (lid < 3) ? pA : pB;
                const int sh   = (lid < 3) ? (10 * lid) : (10 * (lid - 3));
                if (lid < 5)
                    out[(s0 + g) * 5 + lid] = (float)((word >> sh) & 1023);
            }
            return;
        }

        // rare: values exceed a byte -> scalar compares on registers
#pragma unroll
        for (int g = 0; g < 4; ++g) {
            const int4 u = A[2 * g];
            const int4 v = A[2 * g + 1];
            int c0 = (u.x==sp0)+(u.y==sp0)+(u.z==sp0)+(u.w==sp0)
                   + (v.x==sp0)+(v.y==sp0)+(v.z==sp0)+(v.w==sp0);
            int c1 = (u.x==sp1)+(u.y==sp1)+(u.z==sp1)+(u.w==sp1)
                   + (v.x==sp1)+(v.y==sp1)+(v.z==sp1)+(v.w==sp1);
            int c2 = (u.x==sp2)+(u.y==sp2)+(u.z==sp2)+(u.w==sp2)
                   + (v.x==sp2)+(v.y==sp2)+(v.z==sp2)+(v.w==sp2);
            int c3 = (u.x==sp3)+(u.y==sp3)+(u.z==sp3)+(u.w==sp3)
                   + (v.x==sp3)+(v.y==sp3)+(v.z==sp3)+(v.w==sp3);
            int c4 = (u.x==sp4)+(u.y==sp4)+(u.z==sp4)+(u.w==sp4)
                   + (v.x==sp4)+(v.y==sp4)+(v.z==sp4)+(v.w==sp4);
            int pA = c0 | (c1 << 10) | (c2 << 20);
            int pB = c3 | (c4 << 10);
            pA = __reduce_add_sync(0xFFFFFFFFu, pA);
            pB = __reduce_add_sync(0xFFFFFFFFu, pB);
            const int word = (lid < 3) ? pA : pB;
            const int sh   = (lid < 3) ? (10 * lid) : (10 * (lid - 3));
            if (lid < 5)
                out[(s0 + g) * 5 + lid] = (float)((word >> sh) & 1023);
        }
        return;
    }

    // general fallback: per-structure loop (any sizes/alignment)
    for (int g = 0; g < 4; ++g) {
        const int s = s0 + g;
        if (s >= n_structures) break;
        const int start = __shfl_sync(0xFFFFFFFFu, my_off, g);
        const int end   = __shfl_sync(0xFFFFFFFFu, my_off, g + 1);

        int c0 = 0, c1 = 0, c2 = 0, c3 = 0, c4 = 0;
        for (int j = start + lid; j < end; j += 32) {
            const int z = species[j];
            c0 += (z == sp0); c1 += (z == sp1); c2 += (z == sp2);
            c3 += (z == sp3); c4 += (z == sp4);
        }
        c0 = __reduce_add_sync(0xFFFFFFFFu, c0);
        c1 = __reduce_add_sync(0xFFFFFFFFu, c1);
        c2 = __reduce_add_sync(0xFFFFFFFFu, c2);
        c3 = __reduce_add_sync(0xFFFFFFFFu, c3);
        c4 = __reduce_add_sync(0xFFFFFFFFu, c4);
        if (lid == 0) {
            float* o = out + s * 5;
            o[0] = (float)c0; o[1] = (float)c1; o[2] = (float)c2;
            o[3] = (float)c3; o[4] = (float)c4;
        }
    }
}

// Fallback for arbitrary n_species (shared-memory counters, CTA per structure)
__global__ __launch_bounds__(64) void atomic_composition_generic(
    const int* __restrict__ species,
    const void* __restrict__ offsets,
    const int* __restrict__ all_species,
    float* __restrict__ out,
    int n_structures,
    long long n_atoms,
    int n_species)
{
    extern __shared__ int shc[];
    const int s   = blockIdx.x;
    const int tid = threadIdx.x;
    for (int k = tid; k < n_species; k += 64) shc[k] = 0;
    __syncthreads();

    const bool is64 = probe_is64(offsets, n_structures, n_atoms);
    const long long start = is64 ? ((const long long*)offsets)[s]
                                 : (long long)((const int*)offsets)[s];
    long long end = n_atoms;
    if (s + 1 < n_structures)
        end = is64 ? ((const long long*)offsets)[s + 1]
                   : (long long)((const int*)offsets)[s + 1];

    for (long long j = start + tid; j < end; j += 64) {
        const int z = species[j];
        for (int k = 0; k < n_species; ++k)
            if (z == __ldg(&all_species[k])) atomicAdd(&shc[k], 1);
    }
    __syncthreads();
    for (int k = tid; k < n_species; k += 64)
        out[(long long)s * n_species + k] = (float)shc[k];
}

extern "C" void kernel_launch(void* const* d_in, const int* in_sizes, int n_in,
                              void* d_out, int out_size)
{
    const int*  species     = (const int*)d_in[2];
    const void* offsets     = d_in[8];
    const int*  all_species = (const int*)d_in[9];
    float*      out         = (float*)d_out;

    const long long n_atoms      = (long long)in_sizes[2];
    const int       n_structures = in_sizes[8];
    const int       n_species    = in_sizes[9];

    if (n_species == 5 && n_atoms < 0x7FFFFFFFLL) {
        const int warps = (n_structures + 3) / 4;        // 8192
        const int ctas  = (warps * 32 + 511) / 512;      // 512 CTAs x 512 thr
        atomic_composition_simd<<<ctas, 512>>>(
            species, offsets, all_species, out, n_structures, (int)n_atoms);
    } else {
        atomic_composition_generic<<<n_structures, 64, n_species * sizeof(int)>>>(
            species, offsets, all_species, out, n_structures, n_atoms, n_species);
    }
}